// round 9
// baseline (speedup 1.0000x reference)
#include <cuda_runtime.h>
#include <cstdint>

// Problem constants (fixed by the dataset)
#define B_  16
#define D_  128
#define T_  4096
#define K_  1024
#define BT_ (B_*T_)          // 65536 rows
#define R1  256              // pass1 rows per CTA
#define NT1 (BT_/R1)         // 256 pass1 tiles
#define NT2 (BT_/64)         // 1024 pass2 tiles
#define NCAND 8
#define DELTA 1.5e-3f
#define APITCH8 144          // int8 MMA tile row pitch (128B data + 16B pad)
#define P2P 68               // pass2 smem pitch in floats (272B)
#define SXF (127.0f/6.0f)    // x int8 scale
#define WSF 130048.0f        // w int8 scale (1024*127)
#define CINV (-2.0f/(SXF*WSF))

// ---------------------------------------------------------------------------
// Device scratch
// ---------------------------------------------------------------------------
__device__ float g_wnorm[K_];                       // fl32(||w||^2)
__device__ __align__(16) unsigned g_W8u[K_ * 32];   // int8 codebook, packed
__device__ float  g_candv[BT_ * NCAND];
__device__ int    g_candk[BT_ * NCAND];
__device__ double g_part[NT2];

__device__ __forceinline__ uint32_t smem_u32(const void* p) {
    uint32_t a;
    asm("{ .reg .u64 t; cvta.to.shared.u64 t, %1; cvt.u32.u64 %0, t; }" : "=r"(a) : "l"(p));
    return a;
}
__device__ __forceinline__ void cp_async16(uint32_t dst, const void* src) {
    asm volatile("cp.async.cg.shared.global [%0], [%1], 16;" :: "r"(dst), "l"(src));
}
#define CP_COMMIT() asm volatile("cp.async.commit_group;" ::: "memory")
#define CP_WAIT(N)  asm volatile("cp.async.wait_group %0;" :: "n"(N) : "memory")

__device__ __forceinline__ int f2i8(float v) {
    int i = __float2int_rn(v);
    return max(-127, min(127, i));
}

// ascending top-NCAND (strict < keeps earlier/lower-k entry on ties)
__device__ __forceinline__ void insertN(float v, int k, float* cv, int* ck) {
    if (v < cv[NCAND - 1]) {
        cv[NCAND - 1] = v; ck[NCAND - 1] = k;
        #pragma unroll
        for (int a = NCAND - 1; a > 0; a--) {
            bool sw = cv[a] < cv[a - 1];
            float tv = sw ? cv[a] : cv[a - 1];
            float tu = sw ? cv[a - 1] : cv[a];
            int   tk = sw ? ck[a] : ck[a - 1];
            int   tl = sw ? ck[a - 1] : ck[a];
            cv[a - 1] = tv; cv[a] = tu;
            ck[a - 1] = tk; ck[a] = tl;
        }
    }
}

// ---------------------------------------------------------------------------
// Kernel 1: ||w||^2 (fp64->fp32) + int8 codebook (scale WSF).
// ---------------------------------------------------------------------------
__global__ void prep_w_kernel(const float* __restrict__ W) {
    int k = blockIdx.x * 8 + threadIdx.y;
    int lane = threadIdx.x;
    float4 v = *(const float4*)(W + (size_t)k * D_ + lane * 4);
    int i0 = f2i8(v.x * WSF), i1 = f2i8(v.y * WSF), i2 = f2i8(v.z * WSF), i3 = f2i8(v.w * WSF);
    g_W8u[k * 32 + lane] = (unsigned)(i0 & 0xFF) | ((unsigned)(i1 & 0xFF) << 8)
                         | ((unsigned)(i2 & 0xFF) << 16) | ((unsigned)(i3 & 0xFF) << 24);
    double s = (double)v.x * v.x + (double)v.y * v.y
             + (double)v.z * v.z + (double)v.w * v.w;
    #pragma unroll
    for (int o = 16; o > 0; o >>= 1) s += __shfl_down_sync(0xffffffffu, s, o);
    if (lane == 0) g_wnorm[k] = (float)s;
}

// ---------------------------------------------------------------------------
// Kernel 2: IMMA pass-1 (int8 m16n8k32): approx scores + per-row top-8.
// 512 threads / 16 warps x 16 rows, 256-row tile, cp.async double-buffered B.
// smem: sA[256x144] | sB0[128x144] | sB1[128x144] | (staging 64KB overlays
// B0/B1 region during A conversion) | wns[1024]
// ---------------------------------------------------------------------------
#define SM_A    0
#define SM_B0   36864
#define SM_B1   (36864 + 18432)
#define SM_WNS  (36864 + 65536)           // after 64KB staging region
#define SM1_TOT (SM_WNS + 4096)           // 106,496

__global__ void __launch_bounds__(512, 1) hmma_pass1_kernel(const float* __restrict__ x) {
    extern __shared__ char smem[];
    char* sA = smem + SM_A;
    float* wns = (float*)(smem + SM_WNS);
    int tid = threadIdx.x;
    int warp = tid >> 5, lane = tid & 31;
    int blk = blockIdx.x;
    int b = blk >> 4, t0 = (blk & 15) * R1, r0 = blk * R1;

    // --- A tile: two 128-t halves, fp32 staged (overlaying B region), then
    //     transpose-converted to int8 sA[row=t][d] (pitch 144B) ---
    float* xs = (float*)(smem + SM_B0);          // 64KB staging
    const float* xb = x + (size_t)b * D_ * T_ + t0;
    #pragma unroll
    for (int h = 0; h < 2; h++) {
        __syncthreads();
        #pragma unroll
        for (int i = 0; i < 8; i++) {
            int lin = i * 512 + tid;             // 4096 float4 slots
            int d = lin >> 5, t4 = lin & 31;
            *(float4*)(xs + d * 128 + t4 * 4) =
                *(const float4*)(xb + (size_t)d * T_ + h * 128 + t4 * 4);
        }
        __syncthreads();
        int m = tid & 127;                       // t within half
        int cq = tid >> 7;                       // 0..3
        #pragma unroll
        for (int cc = 0; cc < 2; cc++) {
            int c = cq * 2 + cc;                 // 16B chunk 0..7 (16 d each)
            unsigned pk[4];
            #pragma unroll
            for (int u = 0; u < 4; u++) {
                int j = c * 16 + u * 4;
                int a0 = f2i8(xs[(j + 0) * 128 + m] * SXF);
                int a1 = f2i8(xs[(j + 1) * 128 + m] * SXF);
                int a2 = f2i8(xs[(j + 2) * 128 + m] * SXF);
                int a3 = f2i8(xs[(j + 3) * 128 + m] * SXF);
                pk[u] = (unsigned)(a0 & 0xFF) | ((unsigned)(a1 & 0xFF) << 8)
                      | ((unsigned)(a2 & 0xFF) << 16) | ((unsigned)(a3 & 0xFF) << 24);
            }
            *(uint4*)(sA + (h * 128 + m) * APITCH8 + c * 16) = *(uint4*)pk;
        }
    }
    __syncthreads();
    wns[tid] = g_wnorm[tid];
    wns[512 + tid] = g_wnorm[512 + tid];

    uint32_t sAu = smem_u32(sA);
    uint32_t sB0u = smem_u32(smem + SM_B0), sB1u = smem_u32(smem + SM_B1);
    uint32_t aBase = sAu + (warp * 16 + (lane & 15)) * APITCH8 + (lane >> 4) * 16;
    uint32_t bRowOff = ((lane & 7) + ((lane >> 4) << 3)) * APITCH8 + ((lane >> 3) & 1) * 16;

    // A fragments: loaded ONCE, register-resident (16 rows per warp, K=128)
    uint32_t af[4][4];
    #pragma unroll
    for (int ks = 0; ks < 4; ks++)
        asm volatile("ldmatrix.sync.aligned.m8n8.x4.shared.b16 {%0,%1,%2,%3}, [%4];"
            : "=r"(af[ks][0]), "=r"(af[ks][1]), "=r"(af[ks][2]), "=r"(af[ks][3])
            : "r"(aBase + ks * 32));

    float cv0[NCAND], cv1[NCAND]; int ck0[NCAND], ck1[NCAND];
    #pragma unroll
    for (int a = 0; a < NCAND; a++) {
        cv0[a] = 3.4e38f; cv1[a] = 3.4e38f; ck0[a] = 0; ck1[a] = 0;
    }

    // prologue: async-stage B k-tile 0 into buf0 (128 rows x 8 16B-chunks)
    {
        #pragma unroll
        for (int i = 0; i < 2; i++) {
            int s = i * 512 + tid;               // 1024 chunks
            int row = s >> 3, c = s & 7;
            cp_async16(sB0u + row * APITCH8 + c * 16,
                       (const char*)g_W8u + (size_t)row * 128 + c * 16);
        }
        CP_COMMIT();
    }

    for (int kt = 0; kt < 8; kt++) {
        if (kt < 7) {   // prefetch next k-tile into the other buffer
            uint32_t dst = ((kt + 1) & 1) ? sB1u : sB0u;
            const char* src = (const char*)g_W8u + (size_t)(kt + 1) * 128 * 128;
            #pragma unroll
            for (int i = 0; i < 2; i++) {
                int s = i * 512 + tid;
                int row = s >> 3, c = s & 7;
                cp_async16(dst + row * APITCH8 + c * 16, src + (size_t)row * 128 + c * 16);
            }
            CP_COMMIT();
            CP_WAIT(1);
        } else {
            CP_WAIT(0);
        }
        __syncthreads();
        uint32_t sBu = (kt & 1) ? sB1u : sB0u;

        #pragma unroll
        for (int np = 0; np < 8; np++) {
            int acc[2][4];
            #pragma unroll
            for (int h = 0; h < 2; h++)
                #pragma unroll
                for (int q = 0; q < 4; q++) acc[h][q] = 0;

            #pragma unroll
            for (int ks = 0; ks < 4; ks++) {
                uint32_t b0, b1, b2, b3;
                uint32_t baddr = sBu + np * 16 * APITCH8 + ks * 32 + bRowOff;
                asm volatile("ldmatrix.sync.aligned.m8n8.x4.shared.b16 {%0,%1,%2,%3}, [%4];"
                    : "=r"(b0), "=r"(b1), "=r"(b2), "=r"(b3) : "r"(baddr));
                asm volatile("mma.sync.aligned.m16n8k32.row.col.s32.s8.s8.s32 "
                    "{%0,%1,%2,%3}, {%4,%5,%6,%7}, {%8,%9}, {%0,%1,%2,%3};"
                    : "+r"(acc[0][0]), "+r"(acc[0][1]), "+r"(acc[0][2]), "+r"(acc[0][3])
                    : "r"(af[ks][0]), "r"(af[ks][1]), "r"(af[ks][2]), "r"(af[ks][3]),
                      "r"(b0), "r"(b1));
                asm volatile("mma.sync.aligned.m16n8k32.row.col.s32.s8.s8.s32 "
                    "{%0,%1,%2,%3}, {%4,%5,%6,%7}, {%8,%9}, {%0,%1,%2,%3};"
                    : "+r"(acc[1][0]), "+r"(acc[1][1]), "+r"(acc[1][2]), "+r"(acc[1][3])
                    : "r"(af[ks][0]), "r"(af[ks][1]), "r"(af[ks][2]), "r"(af[ks][3]),
                      "r"(b2), "r"(b3));
            }

            // scores: v = wn_k - 2*dot_true = fmaf(CINV, dot_int, wn)
            // list0 row warp*16+(lane>>2); list1 row +8 (I2F exact: |dot|<2^24)
            #pragma unroll
            for (int h = 0; h < 2; h++) {
                int k0 = kt * 128 + np * 16 + h * 8 + 2 * (lane & 3);
                float2 wnp = *(const float2*)(wns + k0);
                insertN(fmaf(CINV, (float)acc[h][0], wnp.x), k0,     cv0, ck0);
                insertN(fmaf(CINV, (float)acc[h][1], wnp.y), k0 + 1, cv0, ck0);
                insertN(fmaf(CINV, (float)acc[h][2], wnp.x), k0,     cv1, ck1);
                insertN(fmaf(CINV, (float)acc[h][3], wnp.y), k0 + 1, cv1, ck1);
            }
        }
        __syncthreads();   // all warps done with buffer before re-stage
    }

    // merge: 4 threads per row -> top-8 per row (reuse smem from start)
    float* mv = (float*)smem;                        // [256][32]
    int*   mk = (int*)(smem + 256 * 32 * 4);         // [256][32]
    __syncthreads();
    {
        int row0 = warp * 16 + (lane >> 2);
        int q = lane & 3;
        #pragma unroll
        for (int a = 0; a < NCAND; a++) {
            mv[row0 * 32 + q * NCAND + a] = cv0[a];  mk[row0 * 32 + q * NCAND + a] = ck0[a];
            mv[(row0 + 8) * 32 + q * NCAND + a] = cv1[a];  mk[(row0 + 8) * 32 + q * NCAND + a] = ck1[a];
        }
    }
    __syncthreads();
    if (tid < 256) {
        float bv[NCAND]; int bk[NCAND];
        #pragma unroll
        for (int a = 0; a < NCAND; a++) { bv[a] = 3.4e38f; bk[a] = 0; }
        #pragma unroll
        for (int i = 0; i < 32; i++)
            insertN(mv[tid * 32 + i], mk[tid * 32 + i], bv, bk);
        int r = r0 + tid;
        #pragma unroll
        for (int a = 0; a < NCAND; a++) {
            g_candv[r * NCAND + a] = bv[a];
            g_candk[r * NCAND + a] = bk[a];
        }
    }
}

// ---------------------------------------------------------------------------
// Kernel 3: fused exact-resolve + gather + output + loss. 64-t tiles, 256 thr.
// dist = fl(fl(xn+wn) - 2*dot_seq), sequential fp32 FMA over d (= reference).
// ---------------------------------------------------------------------------
#define P2T      64
#define SM3_XS   0
#define SM3_QS   (128 * P2P * 4)                 // 34816
#define SM3_IDX  (SM3_QS + 128 * P2P * 4)        // 69632
#define SM3_RED  (SM3_IDX + 256)
#define SM3_TOT  (SM3_RED + 2048)

__global__ void __launch_bounds__(256) pass2_fused_kernel(const float* __restrict__ x,
        const float* __restrict__ W, float* __restrict__ out, float* __restrict__ out_idx_f) {
    extern __shared__ char smem[];
    float* xs = (float*)(smem + SM3_XS);     // [128 d][P2P]
    float* qs = (float*)(smem + SM3_QS);     // [128 d][P2P]
    int* idxs = (int*)(smem + SM3_IDX);
    double* red = (double*)(smem + SM3_RED);
    int tid = threadIdx.x;
    int blk = blockIdx.x;
    int b = blk >> 6, t0 = (blk & 63) * P2T, r0 = blk * P2T;

    const float* xb = x + (size_t)b * D_ * T_ + t0;
    #pragma unroll
    for (int i = 0; i < 8; i++) {
        int lin = i * 256 + tid;
        int d = lin >> 4, t4 = lin & 15;
        *(float4*)(xs + d * P2P + t4 * 4) = *(const float4*)(xb + (size_t)d * T_ + t4 * 4);
    }
    __syncthreads();

    if (tid < P2T) {
        int t = tid, r = r0 + tid;
        // xnorm: double accumulate, round once (whole-ulp-shift invariant)
        double sn = 0.0;
        #pragma unroll 8
        for (int d = 0; d < D_; d++) { float v = xs[d * P2P + t]; sn += (double)v * (double)v; }
        float xn = (float)sn;

        float cvl[NCAND]; int ckl[NCAND];
        #pragma unroll
        for (int a = 0; a < NCAND; a++) { cvl[a] = g_candv[r * NCAND + a]; ckl[a] = g_candk[r * NCAND + a]; }
        float lim = cvl[0] + DELTA;
        float bv = 3.4e38f; int bi = 0x7fffffff;
        if (cvl[NCAND - 1] <= lim) {
            // candidate overflow (p~0): exact full scan, ascending k
            for (int k = 0; k < K_; k++) {
                float acc = 0.f;
                const float* w = W + (size_t)k * D_;
                for (int d = 0; d < D_; d++) acc = fmaf(xs[d * P2P + t], w[d], acc);
                float v = __fsub_rn(__fadd_rn(xn, g_wnorm[k]), 2.0f * acc);
                if (v < bv) { bv = v; bi = k; }
            }
        } else {
            #pragma unroll
            for (int a = 0; a < NCAND; a++) {
                if (cvl[a] <= lim) {
                    int k = ckl[a];
                    float acc = 0.f;
                    const float* w = W + (size_t)k * D_;
                    #pragma unroll 8
                    for (int d = 0; d < D_; d++) acc = fmaf(xs[d * P2P + t], w[d], acc);
                    float v = __fsub_rn(__fadd_rn(xn, g_wnorm[k]), 2.0f * acc);
                    if (v < bv || (v == bv && k < bi)) { bv = v; bi = k; }
                }
            }
        }
        idxs[t] = bi;
        out_idx_f[r] = (float)bi;
    }
    __syncthreads();

    // gather W rows -> qs[d][t]
    #pragma unroll
    for (int i = 0; i < 8; i++) {
        int s = i * 256 + tid;            // 0..2047
        int row = s & 63, c4 = s >> 6;    // c4 0..31
        float4 q = *(const float4*)(W + (size_t)idxs[row] * D_ + c4 * 4);
        qs[(c4 * 4 + 0) * P2P + row] = q.x;
        qs[(c4 * 4 + 1) * P2P + row] = q.y;
        qs[(c4 * 4 + 2) * P2P + row] = q.z;
        qs[(c4 * 4 + 3) * P2P + row] = q.w;
    }
    __syncthreads();

    // write out (coalesced along t) + loss
    double lsum = 0.0;
    int t = tid & 63, dg = tid >> 6;
    float* ob = out + (size_t)b * D_ * T_ + t0;
    #pragma unroll 8
    for (int p = 0; p < 32; p++) {
        int d = dg * 32 + p;
        float xv = xs[d * P2P + t];
        float q  = qs[d * P2P + t];
        float df = __fsub_rn(q, xv);
        ob[(size_t)d * T_ + t] = __fadd_rn(xv, df);   // straight-through rounding
        float sq = __fmul_rn(df, df);
        lsum += (double)sq;
    }
    red[tid] = lsum;
    __syncthreads();
    #pragma unroll
    for (int s = 128; s > 0; s >>= 1) {
        if (tid < s) red[tid] += red[tid + s];
        __syncthreads();
    }
    if (tid == 0) g_part[blk] = red[0];
}

// ---------------------------------------------------------------------------
// Kernel 4: final loss reduction
// ---------------------------------------------------------------------------
__global__ void finish_loss_kernel(float* __restrict__ out) {
    __shared__ double red[256];
    double s = 0.0;
    for (int i = threadIdx.x; i < NT2; i += 256) s += g_part[i];
    red[threadIdx.x] = s;
    __syncthreads();
    #pragma unroll
    for (int st = 128; st > 0; st >>= 1) {
        if (threadIdx.x < st) red[threadIdx.x] += red[threadIdx.x + st];
        __syncthreads();
    }
    if (threadIdx.x == 0) {
        double mean = red[0] / (double)((size_t)B_ * D_ * T_);
        out[(size_t)B_ * D_ * T_ + BT_] = (float)(mean * 0.25);
    }
}

// ---------------------------------------------------------------------------
extern "C" void kernel_launch(void* const* d_in, const int* in_sizes, int n_in,
                              void* d_out, int out_size) {
    const float* x = (const float*)d_in[0];   // (B, D, T) fp32
    const float* W = (const float*)d_in[1];   // (K, D)    fp32
    float* out = (float*)d_out;               // [quantized | indices | loss]

    cudaFuncSetAttribute(hmma_pass1_kernel, cudaFuncAttributeMaxDynamicSharedMemorySize, SM1_TOT);
    cudaFuncSetAttribute(pass2_fused_kernel, cudaFuncAttributeMaxDynamicSharedMemorySize, SM3_TOT);

    prep_w_kernel<<<K_ / 8, dim3(32, 8)>>>(W);
    hmma_pass1_kernel<<<NT1, 512, SM1_TOT>>>(x);
    pass2_fused_kernel<<<NT2, 256, SM3_TOT>>>(x, W, out, out + (size_t)B_ * D_ * T_);
    finish_loss_kernel<<<1, 256>>>(out);
}

// round 10
// speedup vs baseline: 4.4634x; 4.4634x over previous
#include <cuda_runtime.h>
#include <cuda_bf16.h>
#include <cstdint>

// Problem constants (fixed by the dataset)
#define B_  16
#define D_  128
#define T_  4096
#define K_  1024
#define BT_ (B_*T_)          // 65536 rows
#define RC  192              // pass1 rows per CTA (128 HMMA + 64 SIMT)
#define NT1 342              // ceil(BT_/RC)
#define NT2 (BT_/64)         // 1024 pass2 tiles
#define NCAND 6
#define DELTA 3e-4f
#define APITCHB 272          // bf16 MMA tile row pitch
#define XSP 132              // SIMT x tile pitch (words), [t][d]
#define WSP 132              // SIMT w tile pitch (words), [code][d]
#define P2P 68               // pass2 smem pitch in floats

// ---------------------------------------------------------------------------
// Device scratch
// ---------------------------------------------------------------------------
__device__ float  g_wnorm[K_];                           // fl32(||w||^2)
__device__ __align__(16) __nv_bfloat16 g_Wb[K_ * D_];    // bf16 codebook [k][d]
__device__ float  g_candv[BT_ * NCAND];
__device__ int    g_candk[BT_ * NCAND];
__device__ double g_part[NT2];

__device__ __forceinline__ uint32_t smem_u32(const void* p) {
    uint32_t a;
    asm("{ .reg .u64 t; cvta.to.shared.u64 t, %1; cvt.u32.u64 %0, t; }" : "=r"(a) : "l"(p));
    return a;
}
__device__ __forceinline__ void cp_async16(uint32_t dst, const void* src) {
    asm volatile("cp.async.cg.shared.global [%0], [%1], 16;" :: "r"(dst), "l"(src));
}
#define CP_COMMIT() asm volatile("cp.async.commit_group;" ::: "memory")
#define CP_WAIT(N)  asm volatile("cp.async.wait_group %0;" :: "n"(N) : "memory")
#define BAR_H() asm volatile("bar.sync 2, 256;" ::: "memory")   // 8 HMMA warps
#define BAR_S() asm volatile("bar.sync 1, 128;" ::: "memory")   // 4 SIMT warps

// ascending top-6 (strict < keeps earlier entry on ties)
__device__ __forceinline__ void insert6(float v, int k, float* cv, int* ck) {
    if (v < cv[5]) {
        cv[5] = v; ck[5] = k;
        #pragma unroll
        for (int a = 5; a > 0; a--) {
            bool sw = cv[a] < cv[a - 1];
            float tv = sw ? cv[a] : cv[a - 1];
            float tu = sw ? cv[a - 1] : cv[a];
            int   tk = sw ? ck[a] : ck[a - 1];
            int   tl = sw ? ck[a - 1] : ck[a];
            cv[a - 1] = tv; cv[a] = tu;
            ck[a - 1] = tk; ck[a] = tl;
        }
    }
}
// ascending top-3
__device__ __forceinline__ void insert3(float v, int k, float* cv, int* ck) {
    if (v < cv[2]) {
        cv[2] = v; ck[2] = k;
        #pragma unroll
        for (int a = 2; a > 0; a--) {
            bool sw = cv[a] < cv[a - 1];
            float tv = sw ? cv[a] : cv[a - 1];
            float tu = sw ? cv[a - 1] : cv[a];
            int   tk = sw ? ck[a] : ck[a - 1];
            int   tl = sw ? ck[a - 1] : ck[a];
            cv[a - 1] = tv; cv[a] = tu;
            ck[a - 1] = tk; ck[a] = tl;
        }
    }
}

__global__ void dummy_kernel() {}

// ---------------------------------------------------------------------------
// Kernel 1: ||w||^2 (fp64->fp32, correctly rounded) + bf16 codebook.
// ---------------------------------------------------------------------------
__global__ void prep_w_kernel(const float* __restrict__ W) {
    int k = blockIdx.x * 8 + threadIdx.y;
    int lane = threadIdx.x;
    float4 v = *(const float4*)(W + (size_t)k * D_ + lane * 4);
    __nv_bfloat16 b4[4] = { __float2bfloat16(v.x), __float2bfloat16(v.y),
                            __float2bfloat16(v.z), __float2bfloat16(v.w) };
    *(uint2*)(g_Wb + (size_t)k * D_ + lane * 4) = *(uint2*)b4;
    double s = (double)v.x * v.x + (double)v.y * v.y
             + (double)v.z * v.z + (double)v.w * v.w;
    #pragma unroll
    for (int o = 16; o > 0; o >>= 1) s += __shfl_down_sync(0xffffffffu, s, o);
    if (lane == 0) g_wnorm[k] = (float)s;
}

// ---------------------------------------------------------------------------
// Kernel 2: hybrid pass-1. 384 threads = 8 HMMA warps (128 rows, bf16 tensor)
// + 4 SIMT warps (64 rows, fp32 FFMA). Both scan all 1024 codes; tensor and
// fma pipes run concurrently per SM. Output: per-row top-6 candidates.
// smem: sA[128x272 bf16] | xs[64t x 132 fp32] | sB0 | sB1 | ws[64c x 132 fp32] | wns
// ---------------------------------------------------------------------------
#define SM_A    0
#define SM_XS   34816
#define SM_B0   69632
#define SM_B1   104448
#define SM_WS   139264
#define SM_WNS  173056
#define SM1_TOT 177152

__global__ void __launch_bounds__(384, 1) hmma_pass1_kernel(
        const float* __restrict__ x, const float* __restrict__ W) {
    extern __shared__ char smem[];
    char*  sA  = smem + SM_A;
    float* xs  = (float*)(smem + SM_XS);   // [64 t][XSP]  fp32 (SIMT rows)
    float* ws  = (float*)(smem + SM_WS);   // [64 c][WSP]  fp32
    float* wns = (float*)(smem + SM_WNS);
    float* stg = (float*)(smem + SM_B0);   // [128 d][64 t] fp32 staging (transient)
    int tid = threadIdx.x;
    int warp = tid >> 5, lane = tid & 31;
    int blk = blockIdx.x;
    int r0 = blk * RC;

    // ---- HMMA A tile: two 64-row groups staged fp32 then converted to bf16 ----
    #pragma unroll
    for (int g = 0; g < 2; g++) {
        int rr = r0 + g * 64; if (rr > BT_ - 64) rr = BT_ - 64;
        int bb = rr >> 12, tt = rr & (T_ - 1);
        const float* xb = x + (size_t)bb * D_ * T_ + tt;
        __syncthreads();
        #pragma unroll
        for (int i = 0; i < 6; i++) {
            int lin = i * 384 + tid;                 // 2048 float4 chunks
            if (lin < 2048) {
                int d = lin >> 4, t4 = lin & 15;
                *(float4*)(stg + d * 64 + t4 * 4) =
                    *(const float4*)(xb + (size_t)d * T_ + t4 * 4);
            }
        }
        __syncthreads();
        #pragma unroll
        for (int i = 0; i < 3; i++) {
            int task = i * 384 + tid;                // 1024 tasks: 64 rows x 16 chunks
            if (task < 1024) {
                int m = task & 63, c = task >> 6;
                __nv_bfloat16 tmp[8];
                #pragma unroll
                for (int j = 0; j < 8; j++)
                    tmp[j] = __float2bfloat16(stg[(c * 8 + j) * 64 + m]);
                *(uint4*)(sA + (g * 64 + m) * APITCHB + c * 16) = *(uint4*)tmp;
            }
        }
    }
    __syncthreads();
    // ---- SIMT x tile: rows r0+128..r0+191 fp32 -> xs[t][d] (transpose) ----
    {
        int rr = r0 + 128; if (rr > BT_ - 64) rr = BT_ - 64;
        int bb = rr >> 12, tt = rr & (T_ - 1);
        const float* xb = x + (size_t)bb * D_ * T_ + tt;
        #pragma unroll
        for (int i = 0; i < 6; i++) {
            int lin = i * 384 + tid;                 // 2048 float4 chunks
            if (lin < 2048) {
                int d = lin >> 4, t4 = lin & 15;
                float4 v = *(const float4*)(xb + (size_t)d * T_ + t4 * 4);
                xs[(t4 * 4 + 0) * XSP + d] = v.x;
                xs[(t4 * 4 + 1) * XSP + d] = v.y;
                xs[(t4 * 4 + 2) * XSP + d] = v.z;
                xs[(t4 * 4 + 3) * XSP + d] = v.w;
            }
        }
    }
    #pragma unroll
    for (int i = 0; i < 3; i++) {
        int idx = i * 384 + tid;
        if (idx < K_) wns[idx] = g_wnorm[idx];
    }
    __syncthreads();

    if (tid < 256) {
        // ================= HMMA role: 128 rows, all codes =================
        uint32_t sAu = smem_u32(sA);
        uint32_t sB0u = smem_u32(smem + SM_B0), sB1u = smem_u32(smem + SM_B1);
        uint32_t aBase = sAu + (warp * 16 + (lane & 15)) * APITCHB + (lane >> 4) * 16;
        uint32_t bRowOff = ((lane & 7) + (lane >> 4) * 8) * APITCHB + ((lane >> 3) & 1) * 16;

        uint32_t af[8][4];
        #pragma unroll
        for (int ks = 0; ks < 8; ks++)
            asm volatile("ldmatrix.sync.aligned.m8n8.x4.shared.b16 {%0,%1,%2,%3}, [%4];"
                : "=r"(af[ks][0]), "=r"(af[ks][1]), "=r"(af[ks][2]), "=r"(af[ks][3])
                : "r"(aBase + ks * 32));

        float cv0[NCAND], cv1[NCAND]; int ck0[NCAND], ck1[NCAND];
        #pragma unroll
        for (int a = 0; a < NCAND; a++) {
            cv0[a] = 3.4e38f; cv1[a] = 3.4e38f; ck0[a] = 0; ck1[a] = 0;
        }

        // prologue: stage B k-tile 0
        #pragma unroll
        for (int i = 0; i < 8; i++) {
            int s = i * 256 + tid;                   // 2048 chunks
            int row = s >> 4, c = s & 15;
            cp_async16(sB0u + row * APITCHB + c * 16,
                       g_Wb + (size_t)row * D_ + c * 8);
        }
        CP_COMMIT();

        for (int kt = 0; kt < 8; kt++) {
            if (kt < 7) {
                uint32_t dst = ((kt + 1) & 1) ? sB1u : sB0u;
                const __nv_bfloat16* src = g_Wb + (size_t)(kt + 1) * 128 * D_;
                #pragma unroll
                for (int i = 0; i < 8; i++) {
                    int s = i * 256 + tid;
                    int row = s >> 4, c = s & 15;
                    cp_async16(dst + row * APITCHB + c * 16, src + (size_t)row * D_ + c * 8);
                }
                CP_COMMIT();
                CP_WAIT(1);
            } else {
                CP_WAIT(0);
            }
            BAR_H();
            uint32_t sBu = (kt & 1) ? sB1u : sB0u;

            #pragma unroll
            for (int np = 0; np < 8; np++) {
                float acc[2][4];
                #pragma unroll
                for (int h = 0; h < 2; h++)
                    #pragma unroll
                    for (int q = 0; q < 4; q++) acc[h][q] = 0.f;

                #pragma unroll
                for (int ks = 0; ks < 8; ks++) {
                    uint32_t b0, b1, b2, b3;
                    uint32_t baddr = sBu + np * 16 * APITCHB + ks * 32 + bRowOff;
                    asm volatile("ldmatrix.sync.aligned.m8n8.x4.shared.b16 {%0,%1,%2,%3}, [%4];"
                        : "=r"(b0), "=r"(b1), "=r"(b2), "=r"(b3) : "r"(baddr));
                    asm volatile("mma.sync.aligned.m16n8k16.row.col.f32.bf16.bf16.f32 "
                        "{%0,%1,%2,%3}, {%4,%5,%6,%7}, {%8,%9}, {%0,%1,%2,%3};"
                        : "+f"(acc[0][0]), "+f"(acc[0][1]), "+f"(acc[0][2]), "+f"(acc[0][3])
                        : "r"(af[ks][0]), "r"(af[ks][1]), "r"(af[ks][2]), "r"(af[ks][3]),
                          "r"(b0), "r"(b1));
                    asm volatile("mma.sync.aligned.m16n8k16.row.col.f32.bf16.bf16.f32 "
                        "{%0,%1,%2,%3}, {%4,%5,%6,%7}, {%8,%9}, {%0,%1,%2,%3};"
                        : "+f"(acc[1][0]), "+f"(acc[1][1]), "+f"(acc[1][2]), "+f"(acc[1][3])
                        : "r"(af[ks][0]), "r"(af[ks][1]), "r"(af[ks][2]), "r"(af[ks][3]),
                          "r"(b2), "r"(b3));
                }
                #pragma unroll
                for (int h = 0; h < 2; h++) {
                    int k0 = kt * 128 + np * 16 + h * 8 + 2 * (lane & 3);
                    float2 wnp = *(const float2*)(wns + k0);
                    insert6(fmaf(-2.0f, acc[h][0], wnp.x), k0,     cv0, ck0);
                    insert6(fmaf(-2.0f, acc[h][1], wnp.y), k0 + 1, cv0, ck0);
                    insert6(fmaf(-2.0f, acc[h][2], wnp.x), k0,     cv1, ck1);
                    insert6(fmaf(-2.0f, acc[h][3], wnp.y), k0 + 1, cv1, ck1);
                }
            }
            BAR_H();
        }

        // stash HMMA candidate lists (written after the global rejoin below)
        __syncthreads();
        float* mv = (float*)smem;                    // [RC][24]
        int*   mk = (int*)(smem + RC * 24 * 4);
        int row0 = warp * 16 + (lane >> 2);
        int q = lane & 3;
        #pragma unroll
        for (int a = 0; a < NCAND; a++) {
            mv[row0 * 24 + q * 6 + a] = cv0[a];  mk[row0 * 24 + q * 6 + a] = ck0[a];
            mv[(row0 + 8) * 24 + q * 6 + a] = cv1[a];  mk[(row0 + 8) * 24 + q * 6 + a] = ck1[a];
        }
    } else {
        // ================= SIMT role: 64 rows, all codes, fp32 =================
        int sid = tid - 256;                 // 0..127
        int ty = sid >> 3;                   // 0..15 -> rows 128 + ty*4
        int tx = sid & 7;                    // codes tx + 8j within s-tile
        uint32_t wsu = smem_u32(ws);

        float cvS[4][3]; int ckS[4][3];
        #pragma unroll
        for (int i2 = 0; i2 < 4; i2++)
            #pragma unroll
            for (int a = 0; a < 3; a++) { cvS[i2][a] = 3.4e38f; ckS[i2][a] = 0; }

        for (int st = 0; st < 16; st++) {
            // stage 64-code fp32 W s-tile
            #pragma unroll
            for (int i = 0; i < 16; i++) {
                int s = i * 128 + sid;               // 2048 chunks
                int row = s >> 5, c = s & 31;
                cp_async16(wsu + row * (WSP * 4) + c * 16,
                           W + (size_t)(st * 64 + row) * D_ + c * 4);
            }
            CP_COMMIT(); CP_WAIT(0);
            BAR_S();

            float acc[4][8];
            #pragma unroll
            for (int i2 = 0; i2 < 4; i2++)
                #pragma unroll
                for (int j = 0; j < 8; j++) acc[i2][j] = 0.f;

            for (int dc = 0; dc < D_; dc += 4) {     // 4-d chunks, d ascending
                float4 xr[4], wr[8];
                #pragma unroll
                for (int i2 = 0; i2 < 4; i2++)
                    xr[i2] = *(const float4*)(xs + (ty * 4 + i2) * XSP + dc);
                #pragma unroll
                for (int j = 0; j < 8; j++)
                    wr[j] = *(const float4*)(ws + (tx + 8 * j) * WSP + dc);
                #pragma unroll
                for (int i2 = 0; i2 < 4; i2++) {
                    #pragma unroll
                    for (int j = 0; j < 8; j++) {
                        float a0 = fmaf(xr[i2].x, wr[j].x, acc[i2][j]);
                        float a1 = fmaf(xr[i2].y, wr[j].y, a0);
                        float a2 = fmaf(xr[i2].z, wr[j].z, a1);
                        acc[i2][j] = fmaf(xr[i2].w, wr[j].w, a2);
                    }
                }
            }
            // fold scores
            #pragma unroll
            for (int j = 0; j < 8; j++) {
                int c = st * 64 + tx + 8 * j;
                float wn = wns[c];
                #pragma unroll
                for (int i2 = 0; i2 < 4; i2++)
                    insert3(fmaf(-2.0f, acc[i2][j], wn), c, cvS[i2], ckS[i2]);
            }
            BAR_S();   // done reading ws before next stage
        }

        __syncthreads();
        float* mv = (float*)smem;
        int*   mk = (int*)(smem + RC * 24 * 4);
        #pragma unroll
        for (int i2 = 0; i2 < 4; i2++)
            #pragma unroll
            for (int a = 0; a < 3; a++) {
                int row = 128 + ty * 4 + i2;
                mv[row * 24 + tx * 3 + a] = cvS[i2][a];
                mk[row * 24 + tx * 3 + a] = ckS[i2][a];
            }
    }
    __syncthreads();

    // final per-row merge: 24 entries -> top-6
    if (tid < RC) {
        float* mv = (float*)smem;
        int*   mk = (int*)(smem + RC * 24 * 4);
        float bv[NCAND]; int bk[NCAND];
        #pragma unroll
        for (int a = 0; a < NCAND; a++) { bv[a] = 3.4e38f; bk[a] = 0; }
        #pragma unroll
        for (int i = 0; i < 24; i++)
            insert6(mv[tid * 24 + i], mk[tid * 24 + i], bv, bk);
        int r = r0 + tid;
        if (r < BT_) {
            #pragma unroll
            for (int a = 0; a < NCAND; a++) {
                g_candv[r * NCAND + a] = bv[a];
                g_candk[r * NCAND + a] = bk[a];
            }
        }
    }
}

// ---------------------------------------------------------------------------
// Kernel 3: fused exact-resolve + gather + output + loss. 64-t tiles, 256 thr.
// dist = fl(fl(xn+wn) - 2*dot_seq), sequential fp32 FMA over d (= reference).
// ---------------------------------------------------------------------------
#define P2T      64
#define SM3_XS   0
#define SM3_QS   (128 * P2P * 4)
#define SM3_IDX  (SM3_QS + 128 * P2P * 4)
#define SM3_RED  (SM3_IDX + 256)
#define SM3_TOT  (SM3_RED + 2048)

__global__ void __launch_bounds__(256) pass2_fused_kernel(const float* __restrict__ x,
        const float* __restrict__ W, float* __restrict__ out, float* __restrict__ out_idx_f) {
    extern __shared__ char smem[];
    float* xs = (float*)(smem + SM3_XS);
    float* qs = (float*)(smem + SM3_QS);
    int* idxs = (int*)(smem + SM3_IDX);
    double* red = (double*)(smem + SM3_RED);
    int tid = threadIdx.x;
    int blk = blockIdx.x;
    int b = blk >> 6, t0 = (blk & 63) * P2T, r0 = blk * P2T;

    const float* xb = x + (size_t)b * D_ * T_ + t0;
    #pragma unroll
    for (int i = 0; i < 8; i++) {
        int lin = i * 256 + tid;
        int d = lin >> 4, t4 = lin & 15;
        *(float4*)(xs + d * P2P + t4 * 4) = *(const float4*)(xb + (size_t)d * T_ + t4 * 4);
    }
    __syncthreads();

    if (tid < P2T) {
        int t = tid, r = r0 + tid;
        double sn = 0.0;
        #pragma unroll 8
        for (int d = 0; d < D_; d++) { float v = xs[d * P2P + t]; sn += (double)v * (double)v; }
        float xn = (float)sn;

        float cvl[NCAND]; int ckl[NCAND];
        #pragma unroll
        for (int a = 0; a < NCAND; a++) { cvl[a] = g_candv[r * NCAND + a]; ckl[a] = g_candk[r * NCAND + a]; }
        float lim = cvl[0] + DELTA;
        float bv = 3.4e38f; int bi = 0x7fffffff;
        if (cvl[NCAND - 1] <= lim) {
            for (int k = 0; k < K_; k++) {
                float acc = 0.f;
                const float* w = W + (size_t)k * D_;
                for (int d = 0; d < D_; d++) acc = fmaf(xs[d * P2P + t], w[d], acc);
                float v = __fsub_rn(__fadd_rn(xn, g_wnorm[k]), 2.0f * acc);
                if (v < bv) { bv = v; bi = k; }
            }
        } else {
            #pragma unroll
            for (int a = 0; a < NCAND; a++) {
                if (cvl[a] <= lim) {
                    int k = ckl[a];
                    float acc = 0.f;
                    const float* w = W + (size_t)k * D_;
                    #pragma unroll 8
                    for (int d = 0; d < D_; d++) acc = fmaf(xs[d * P2P + t], w[d], acc);
                    float v = __fsub_rn(__fadd_rn(xn, g_wnorm[k]), 2.0f * acc);
                    if (v < bv || (v == bv && k < bi)) { bv = v; bi = k; }
                }
            }
        }
        idxs[t] = bi;
        out_idx_f[r] = (float)bi;
    }
    __syncthreads();

    #pragma unroll
    for (int i = 0; i < 8; i++) {
        int s = i * 256 + tid;
        int row = s & 63, c4 = s >> 6;
        float4 q = *(const float4*)(W + (size_t)idxs[row] * D_ + c4 * 4);
        qs[(c4 * 4 + 0) * P2P + row] = q.x;
        qs[(c4 * 4 + 1) * P2P + row] = q.y;
        qs[(c4 * 4 + 2) * P2P + row] = q.z;
        qs[(c4 * 4 + 3) * P2P + row] = q.w;
    }
    __syncthreads();

    double lsum = 0.0;
    int t = tid & 63, dg = tid >> 6;
    float* ob = out + (size_t)b * D_ * T_ + t0;
    #pragma unroll 8
    for (int p = 0; p < 32; p++) {
        int d = dg * 32 + p;
        float xv = xs[d * P2P + t];
        float q  = qs[d * P2P + t];
        float df = __fsub_rn(q, xv);
        ob[(size_t)d * T_ + t] = __fadd_rn(xv, df);
        float sq = __fmul_rn(df, df);
        lsum += (double)sq;
    }
    red[tid] = lsum;
    __syncthreads();
    #pragma unroll
    for (int s = 128; s > 0; s >>= 1) {
        if (tid < s) red[tid] += red[tid + s];
        __syncthreads();
    }
    if (tid == 0) g_part[blk] = red[0];
}

// ---------------------------------------------------------------------------
// Kernel 4: final loss reduction
// ---------------------------------------------------------------------------
__global__ void finish_loss_kernel(float* __restrict__ out) {
    __shared__ double red[256];
    double s = 0.0;
    for (int i = threadIdx.x; i < NT2; i += 256) s += g_part[i];
    red[threadIdx.x] = s;
    __syncthreads();
    #pragma unroll
    for (int st = 128; st > 0; st >>= 1) {
        if (threadIdx.x < st) red[threadIdx.x] += red[threadIdx.x + st];
        __syncthreads();
    }
    if (threadIdx.x == 0) {
        double mean = red[0] / (double)((size_t)B_ * D_ * T_);
        out[(size_t)B_ * D_ * T_ + BT_] = (float)(mean * 0.25);
    }
}

// ---------------------------------------------------------------------------
extern "C" void kernel_launch(void* const* d_in, const int* in_sizes, int n_in,
                              void* d_out, int out_size) {
    const float* x = (const float*)d_in[0];   // (B, D, T) fp32
    const float* W = (const float*)d_in[1];   // (K, D)    fp32
    float* out = (float*)d_out;               // [quantized | indices | loss]

    cudaFuncSetAttribute(hmma_pass1_kernel, cudaFuncAttributeMaxDynamicSharedMemorySize, SM1_TOT);
    cudaFuncSetAttribute(pass2_fused_kernel, cudaFuncAttributeMaxDynamicSharedMemorySize, SM3_TOT);

    prep_w_kernel<<<K_ / 8, dim3(32, 8)>>>(W);
    dummy_kernel<<<1, 32>>>();                 // shift ncu capture slot
    dummy_kernel<<<1, 32>>>();                 // so launch #4 = pass1
    hmma_pass1_kernel<<<NT1, 384, SM1_TOT>>>(x, W);
    pass2_fused_kernel<<<NT2, 256, SM3_TOT>>>(x, W, out, out + (size_t)B_ * D_ * T_);
    finish_loss_kernel<<<1, 256>>>(out);
}

// round 11
// speedup vs baseline: 7.4055x; 1.6591x over previous
#include <cuda_runtime.h>
#include <cuda_bf16.h>
#include <cstdint>

// Problem constants (fixed by the dataset)
#define B_  16
#define D_  128
#define T_  4096
#define K_  1024
#define BT_ (B_*T_)          // 65536 rows
#define NT1 (BT_/128)        // 512 pass1 tiles (128 rows each)
#define NT2 (BT_/64)         // 1024 pass2 tiles
#define NCAND 6
#define DELTA 3e-4f
#define APITCHB 272          // bf16 MMA tile row pitch
#define P2P 68               // pass2 smem pitch in floats

// ---------------------------------------------------------------------------
// Device scratch
// ---------------------------------------------------------------------------
__device__ float  g_wnorm[K_];                           // fl32(||w||^2)
__device__ __align__(16) __nv_bfloat16 g_Wb[K_ * D_];    // bf16 codebook [k][d]
__device__ float  g_candv[BT_ * NCAND];
__device__ int    g_candk[BT_ * NCAND];
__device__ double g_part[NT2];

__device__ __forceinline__ uint32_t smem_u32(const void* p) {
    uint32_t a;
    asm("{ .reg .u64 t; cvta.to.shared.u64 t, %1; cvt.u32.u64 %0, t; }" : "=r"(a) : "l"(p));
    return a;
}
__device__ __forceinline__ void cp_async16(uint32_t dst, const void* src) {
    asm volatile("cp.async.cg.shared.global [%0], [%1], 16;" :: "r"(dst), "l"(src));
}
#define CP_COMMIT() asm volatile("cp.async.commit_group;" ::: "memory")
#define CP_WAIT(N)  asm volatile("cp.async.wait_group %0;" :: "n"(N) : "memory")

// ascending top-6 (strict < keeps earlier/lower-k entry on ties)
__device__ __forceinline__ void insert6(float v, int k, float* cv, int* ck) {
    if (v < cv[5]) {
        cv[5] = v; ck[5] = k;
        #pragma unroll
        for (int a = 5; a > 0; a--) {
            bool sw = cv[a] < cv[a - 1];
            float tv = sw ? cv[a] : cv[a - 1];
            float tu = sw ? cv[a - 1] : cv[a];
            int   tk = sw ? ck[a] : ck[a - 1];
            int   tl = sw ? ck[a - 1] : ck[a];
            cv[a - 1] = tv; cv[a] = tu;
            ck[a - 1] = tk; ck[a] = tl;
        }
    }
}

__global__ void dummy_kernel() {}

// ---------------------------------------------------------------------------
// Kernel 1: ||w||^2 (fp64->fp32, correctly rounded) + bf16 codebook.
// ---------------------------------------------------------------------------
__global__ void prep_w_kernel(const float* __restrict__ W) {
    int k = blockIdx.x * 8 + threadIdx.y;
    int lane = threadIdx.x;
    float4 v = *(const float4*)(W + (size_t)k * D_ + lane * 4);
    __nv_bfloat16 b4[4] = { __float2bfloat16(v.x), __float2bfloat16(v.y),
                            __float2bfloat16(v.z), __float2bfloat16(v.w) };
    *(uint2*)(g_Wb + (size_t)k * D_ + lane * 4) = *(uint2*)b4;
    double s = (double)v.x * v.x + (double)v.y * v.y
             + (double)v.z * v.z + (double)v.w * v.w;
    #pragma unroll
    for (int o = 16; o > 0; o >>= 1) s += __shfl_down_sync(0xffffffffu, s, o);
    if (lane == 0) g_wnorm[k] = (float)s;
}

// ---------------------------------------------------------------------------
// Kernel 2: HMMA pass-1 v4 — 16 independent accumulator chains per warp.
// 256 threads = 8 warps x 16 rows. acc[np 0..7][h 0..1] held across the full
// ks loop so up to 16 MMAs per warp are in flight (latency-chain saturation).
// smem: sA[128x272] | sB0 | sB1 (fp32 x staging overlays B0+B1) | wns[1024]
// ---------------------------------------------------------------------------
#define SM_A    0
#define SM_B0   34816
#define SM_B1   (34816 + 34816)
#define SM_WNS  (34816 + 69632)
#define SM1_TOT (SM_WNS + 4096)     // 108,544 -> 2 CTAs/SM

__global__ void __launch_bounds__(256, 2) hmma_pass1_kernel(const float* __restrict__ x) {
    extern __shared__ char smem[];
    char* sA = smem + SM_A;
    float* xs  = (float*)(smem + SM_B0);        // [128 d][128 t] fp32 staging
    float* wns = (float*)(smem + SM_WNS);       // [1024]
    int tid = threadIdx.x;
    int warp = tid >> 5, lane = tid & 31;
    int blk = blockIdx.x;
    int b = blk >> 5, t0 = (blk & 31) * 128, r0 = blk * 128;

    // --- stage x tile fp32 (coalesced along t), overlaying B buffers ---
    const float* xb = x + (size_t)b * D_ * T_ + t0;
    #pragma unroll
    for (int i = 0; i < 16; i++) {
        int lin = i * 256 + tid;
        int d = lin >> 5, t4 = lin & 31;
        *(float4*)(xs + d * 128 + t4 * 4) = *(const float4*)(xb + (size_t)d * T_ + t4 * 4);
    }
    __syncthreads();
    // --- transpose-convert to bf16 A tile: sA[row=t][d] ---
    {
        int m = tid >> 1, half = tid & 1;
        #pragma unroll
        for (int cc = 0; cc < 8; cc++) {
            int c = half * 8 + cc;
            __nv_bfloat16 tmp[8];
            #pragma unroll
            for (int j = 0; j < 8; j++) tmp[j] = __float2bfloat16(xs[(c * 8 + j) * 128 + m]);
            *(uint4*)(sA + m * APITCHB + c * 16) = *(uint4*)tmp;
        }
    }
    __syncthreads();
    #pragma unroll
    for (int i = 0; i < 4; i++) wns[i * 256 + tid] = g_wnorm[i * 256 + tid];

    uint32_t sAu = smem_u32(sA);
    uint32_t sB0u = smem_u32(smem + SM_B0), sB1u = smem_u32(smem + SM_B1);
    uint32_t aBase = sAu + (warp * 16 + (lane & 15)) * APITCHB + (lane >> 4) * 16;
    uint32_t bRowOff = ((lane & 7) + (lane >> 4) * 8) * APITCHB + ((lane >> 3) & 1) * 16;

    float cv0[NCAND], cv1[NCAND]; int ck0[NCAND], ck1[NCAND];
    #pragma unroll
    for (int a = 0; a < NCAND; a++) {
        cv0[a] = 3.4e38f; cv1[a] = 3.4e38f; ck0[a] = 0; ck1[a] = 0;
    }

    // prologue: async-stage B k-tile 0 into buf0
    #pragma unroll
    for (int i = 0; i < 8; i++) {
        int s = i * 256 + tid;                   // 2048 16B chunks
        int row = s >> 4, c = s & 15;
        cp_async16(sB0u + row * APITCHB + c * 16, g_Wb + (size_t)row * D_ + c * 8);
    }
    CP_COMMIT();

    for (int kt = 0; kt < 8; kt++) {
        if (kt < 7) {   // prefetch next k-tile into the other buffer
            uint32_t dst = ((kt + 1) & 1) ? sB1u : sB0u;
            const __nv_bfloat16* src = g_Wb + (size_t)(kt + 1) * 128 * D_;
            #pragma unroll
            for (int i = 0; i < 8; i++) {
                int s = i * 256 + tid;
                int row = s >> 4, c = s & 15;
                cp_async16(dst + row * APITCHB + c * 16, src + (size_t)row * D_ + c * 8);
            }
            CP_COMMIT();
            CP_WAIT(1);
        } else {
            CP_WAIT(0);
        }
        __syncthreads();
        uint32_t sBu = (kt & 1) ? sB1u : sB0u;

        // 16 independent accumulator chains: acc[np][h]
        float acc[8][2][4];
        #pragma unroll
        for (int np = 0; np < 8; np++)
            #pragma unroll
            for (int h = 0; h < 2; h++)
                #pragma unroll
                for (int q = 0; q < 4; q++) acc[np][h][q] = 0.f;

        #pragma unroll
        for (int ks = 0; ks < 8; ks++) {
            uint32_t af0, af1, af2, af3;
            asm volatile("ldmatrix.sync.aligned.m8n8.x4.shared.b16 {%0,%1,%2,%3}, [%4];"
                : "=r"(af0), "=r"(af1), "=r"(af2), "=r"(af3) : "r"(aBase + ks * 32));
            uint32_t bc[4], bn[4];
            asm volatile("ldmatrix.sync.aligned.m8n8.x4.shared.b16 {%0,%1,%2,%3}, [%4];"
                : "=r"(bc[0]), "=r"(bc[1]), "=r"(bc[2]), "=r"(bc[3])
                : "r"(sBu + ks * 32 + bRowOff));
            #pragma unroll
            for (int np = 0; np < 8; np++) {
                if (np < 7) {
                    asm volatile("ldmatrix.sync.aligned.m8n8.x4.shared.b16 {%0,%1,%2,%3}, [%4];"
                        : "=r"(bn[0]), "=r"(bn[1]), "=r"(bn[2]), "=r"(bn[3])
                        : "r"(sBu + (np + 1) * 16 * APITCHB + ks * 32 + bRowOff));
                }
                asm volatile("mma.sync.aligned.m16n8k16.row.col.f32.bf16.bf16.f32 "
                    "{%0,%1,%2,%3}, {%4,%5,%6,%7}, {%8,%9}, {%0,%1,%2,%3};"
                    : "+f"(acc[np][0][0]), "+f"(acc[np][0][1]), "+f"(acc[np][0][2]), "+f"(acc[np][0][3])
                    : "r"(af0), "r"(af1), "r"(af2), "r"(af3), "r"(bc[0]), "r"(bc[1]));
                asm volatile("mma.sync.aligned.m16n8k16.row.col.f32.bf16.bf16.f32 "
                    "{%0,%1,%2,%3}, {%4,%5,%6,%7}, {%8,%9}, {%0,%1,%2,%3};"
                    : "+f"(acc[np][1][0]), "+f"(acc[np][1][1]), "+f"(acc[np][1][2]), "+f"(acc[np][1][3])
                    : "r"(af0), "r"(af1), "r"(af2), "r"(af3), "r"(bc[2]), "r"(bc[3]));
                #pragma unroll
                for (int q = 0; q < 4; q++) bc[q] = bn[q];
            }
        }

        // scores: v = wn_k - 2*dot; list0 row warp*16+(lane>>2), list1 row +8
        #pragma unroll
        for (int np = 0; np < 8; np++) {
            #pragma unroll
            for (int h = 0; h < 2; h++) {
                int k0 = kt * 128 + np * 16 + h * 8 + 2 * (lane & 3);
                float2 wnp = *(const float2*)(wns + k0);
                insert6(fmaf(-2.0f, acc[np][h][0], wnp.x), k0,     cv0, ck0);
                insert6(fmaf(-2.0f, acc[np][h][1], wnp.y), k0 + 1, cv0, ck0);
                insert6(fmaf(-2.0f, acc[np][h][2], wnp.x), k0,     cv1, ck1);
                insert6(fmaf(-2.0f, acc[np][h][3], wnp.y), k0 + 1, cv1, ck1);
            }
        }
        __syncthreads();   // all warps done with buffer before next re-stage
    }

    // merge: 4 threads per row -> top-6 per row (reuse sA region)
    float* mv = (float*)smem;                    // [128][24]
    int*   mk = (int*)(smem + 128 * 24 * 4);
    __syncthreads();
    {
        int row0 = warp * 16 + (lane >> 2);
        int q = lane & 3;
        #pragma unroll
        for (int a = 0; a < NCAND; a++) {
            mv[row0 * 24 + q * 6 + a] = cv0[a];  mk[row0 * 24 + q * 6 + a] = ck0[a];
            mv[(row0 + 8) * 24 + q * 6 + a] = cv1[a];  mk[(row0 + 8) * 24 + q * 6 + a] = ck1[a];
        }
    }
    __syncthreads();
    if (tid < 128) {
        float bv[NCAND]; int bk[NCAND];
        #pragma unroll
        for (int a = 0; a < NCAND; a++) { bv[a] = 3.4e38f; bk[a] = 0; }
        #pragma unroll
        for (int i = 0; i < 24; i++)
            insert6(mv[tid * 24 + i], mk[tid * 24 + i], bv, bk);
        int r = r0 + tid;
        #pragma unroll
        for (int a = 0; a < NCAND; a++) {
            g_candv[r * NCAND + a] = bv[a];
            g_candk[r * NCAND + a] = bk[a];
        }
    }
}

// ---------------------------------------------------------------------------
// Kernel 3: fused exact-resolve + gather + output + loss. 64-t tiles, 256 thr.
// dist = fl(fl(xn+wn) - 2*dot_seq), sequential fp32 FMA over d (= reference).
// ---------------------------------------------------------------------------
#define P2T      64
#define SM3_XS   0
#define SM3_QS   (128 * P2P * 4)
#define SM3_IDX  (SM3_QS + 128 * P2P * 4)
#define SM3_RED  (SM3_IDX + 256)
#define SM3_TOT  (SM3_RED + 2048)

__global__ void __launch_bounds__(256) pass2_fused_kernel(const float* __restrict__ x,
        const float* __restrict__ W, float* __restrict__ out, float* __restrict__ out_idx_f) {
    extern __shared__ char smem[];
    float* xs = (float*)(smem + SM3_XS);
    float* qs = (float*)(smem + SM3_QS);
    int* idxs = (int*)(smem + SM3_IDX);
    double* red = (double*)(smem + SM3_RED);
    int tid = threadIdx.x;
    int blk = blockIdx.x;
    int b = blk >> 6, t0 = (blk & 63) * P2T, r0 = blk * P2T;

    const float* xb = x + (size_t)b * D_ * T_ + t0;
    #pragma unroll
    for (int i = 0; i < 8; i++) {
        int lin = i * 256 + tid;
        int d = lin >> 4, t4 = lin & 15;
        *(float4*)(xs + d * P2P + t4 * 4) = *(const float4*)(xb + (size_t)d * T_ + t4 * 4);
    }
    __syncthreads();

    if (tid < P2T) {
        int t = tid, r = r0 + tid;
        double sn = 0.0;
        #pragma unroll 8
        for (int d = 0; d < D_; d++) { float v = xs[d * P2P + t]; sn += (double)v * (double)v; }
        float xn = (float)sn;

        float cvl[NCAND]; int ckl[NCAND];
        #pragma unroll
        for (int a = 0; a < NCAND; a++) { cvl[a] = g_candv[r * NCAND + a]; ckl[a] = g_candk[r * NCAND + a]; }
        float lim = cvl[0] + DELTA;
        float bv = 3.4e38f; int bi = 0x7fffffff;
        if (cvl[NCAND - 1] <= lim) {
            for (int k = 0; k < K_; k++) {
                float acc = 0.f;
                const float* w = W + (size_t)k * D_;
                for (int d = 0; d < D_; d++) acc = fmaf(xs[d * P2P + t], w[d], acc);
                float v = __fsub_rn(__fadd_rn(xn, g_wnorm[k]), 2.0f * acc);
                if (v < bv) { bv = v; bi = k; }
            }
        } else {
            #pragma unroll
            for (int a = 0; a < NCAND; a++) {
                if (cvl[a] <= lim) {
                    int k = ckl[a];
                    float acc = 0.f;
                    const float* w = W + (size_t)k * D_;
                    #pragma unroll 8
                    for (int d = 0; d < D_; d++) acc = fmaf(xs[d * P2P + t], w[d], acc);
                    float v = __fsub_rn(__fadd_rn(xn, g_wnorm[k]), 2.0f * acc);
                    if (v < bv || (v == bv && k < bi)) { bv = v; bi = k; }
                }
            }
        }
        idxs[t] = bi;
        out_idx_f[r] = (float)bi;
    }
    __syncthreads();

    #pragma unroll
    for (int i = 0; i < 8; i++) {
        int s = i * 256 + tid;
        int row = s & 63, c4 = s >> 6;
        float4 q = *(const float4*)(W + (size_t)idxs[row] * D_ + c4 * 4);
        qs[(c4 * 4 + 0) * P2P + row] = q.x;
        qs[(c4 * 4 + 1) * P2P + row] = q.y;
        qs[(c4 * 4 + 2) * P2P + row] = q.z;
        qs[(c4 * 4 + 3) * P2P + row] = q.w;
    }
    __syncthreads();

    double lsum = 0.0;
    int t = tid & 63, dg = tid >> 6;
    float* ob = out + (size_t)b * D_ * T_ + t0;
    #pragma unroll 8
    for (int p = 0; p < 32; p++) {
        int d = dg * 32 + p;
        float xv = xs[d * P2P + t];
        float q  = qs[d * P2P + t];
        float df = __fsub_rn(q, xv);
        ob[(size_t)d * T_ + t] = __fadd_rn(xv, df);
        float sq = __fmul_rn(df, df);
        lsum += (double)sq;
    }
    red[tid] = lsum;
    __syncthreads();
    #pragma unroll
    for (int s = 128; s > 0; s >>= 1) {
        if (tid < s) red[tid] += red[tid + s];
        __syncthreads();
    }
    if (tid == 0) g_part[blk] = red[0];
}

// ---------------------------------------------------------------------------
// Kernel 4: final loss reduction
// ---------------------------------------------------------------------------
__global__ void finish_loss_kernel(float* __restrict__ out) {
    __shared__ double red[256];
    double s = 0.0;
    for (int i = threadIdx.x; i < NT2; i += 256) s += g_part[i];
    red[threadIdx.x] = s;
    __syncthreads();
    #pragma unroll
    for (int st = 128; st > 0; st >>= 1) {
        if (threadIdx.x < st) red[threadIdx.x] += red[threadIdx.x + st];
        __syncthreads();
    }
    if (threadIdx.x == 0) {
        double mean = red[0] / (double)((size_t)B_ * D_ * T_);
        out[(size_t)B_ * D_ * T_ + BT_] = (float)(mean * 0.25);
    }
}

// ---------------------------------------------------------------------------
extern "C" void kernel_launch(void* const* d_in, const int* in_sizes, int n_in,
                              void* d_out, int out_size) {
    const float* x = (const float*)d_in[0];   // (B, D, T) fp32
    const float* W = (const float*)d_in[1];   // (K, D)    fp32
    float* out = (float*)d_out;               // [quantized | indices | loss]

    cudaFuncSetAttribute(hmma_pass1_kernel, cudaFuncAttributeMaxDynamicSharedMemorySize, SM1_TOT);
    cudaFuncSetAttribute(pass2_fused_kernel, cudaFuncAttributeMaxDynamicSharedMemorySize, SM3_TOT);

    prep_w_kernel<<<K_ / 8, dim3(32, 8)>>>(W);
    dummy_kernel<<<1, 32>>>();                 // keep ncu capture slot #4
    dummy_kernel<<<1, 32>>>();                 // = pass1
    hmma_pass1_kernel<<<NT1, 256, SM1_TOT>>>(x);
    pass2_fused_kernel<<<NT2, 256, SM3_TOT>>>(x, W, out, out + (size_t)B_ * D_ * T_);
    finish_loss_kernel<<<1, 256>>>(out);
}